// round 3
// baseline (speedup 1.0000x reference)
#include <cuda_runtime.h>
#include <cuda_bf16.h>

// BilateralGridCP4D fused eval, 1 point/thread.
// Round-3 change: cut per-thread LDS instruction count 141 -> ~46 via
//   - float2 pair-tables for the 4 interp axes (conflict-free)
//   - transposed fac0 in float4 (uniform broadcast LDS.128)
//   - packed MLP weights (w1 row + b1) as float4

#define RANK 5
#define THREADS 256

__device__ __forceinline__ void interp_mul_pt(const float2* __restrict__ pt, int D,
                                              float pos, float coef[RANK], bool first)
{
    pos = fminf(fmaxf(pos, 0.0f), (float)(D - 1));
    int i0 = (int)pos;
    if (i0 > D - 2) i0 = D - 2;
    float w = pos - (float)i0;
    const float2* p = pt + i0 * RANK;
#pragma unroll
    for (int r = 0; r < RANK; r++) {
        float2 f = p[r];
        float val = fmaf(w, f.y - f.x, f.x);   // f0*(1-w) + f1*w
        if (first) coef[r] = val;
        else       coef[r] *= val;
    }
}

// tanh(2a) = 1 - 2/(exp(4a)+1), via MUFU. Rel err ~1e-6.
__device__ __forceinline__ float fast_tanh2(float a)
{
    float e = __expf(4.0f * a);
    return 1.0f - __fdividef(2.0f, e + 1.0f);
}

__global__ __launch_bounds__(THREADS)
void bgrid_cp4d_kernel(const float* __restrict__ xyz,
                       const float* __restrict__ rgb,
                       const float* __restrict__ fac0,  // (12,5)
                       const float* __restrict__ fac1,  // (5,8)
                       const float* __restrict__ fac2,  // (5,16)
                       const float* __restrict__ fac3,  // (5,16)
                       const float* __restrict__ fac4,  // (5,16)
                       const float* __restrict__ w1,    // (8,3)
                       const float* __restrict__ b1,    // (8,)
                       const float* __restrict__ w2,    // (1,8)
                       const float* __restrict__ b2,    // (1,)
                       float4* __restrict__ out4,       // N*3 float4
                       int npts)
{
    // pair tables: pt[i*RANK + r] = (fac[r][i], fac[r][i+1])
    __shared__ float2 s_t1[7 * RANK];    // D=8
    __shared__ float2 s_t2[15 * RANK];   // D=16
    __shared__ float2 s_t3[15 * RANK];
    __shared__ float2 s_t4[15 * RANK];
    __shared__ float4 s_fac0[15];        // [r*3+q] = fac0 cols 4q..4q+3 of rank r
    __shared__ float4 s_mw[8];           // (w1[h][0..2], b1[h])
    __shared__ float4 s_w2[2];
    __shared__ float  s_b2;

    int tid = threadIdx.x;
    if (tid < 35) {                      // fac1 pair table
        int i = tid / RANK, r = tid % RANK;
        s_t1[tid] = make_float2(fac1[r * 8 + i], fac1[r * 8 + i + 1]);
    }
    if (tid < 75) {                      // fac2
        int i = tid / RANK, r = tid % RANK;
        s_t2[tid] = make_float2(fac2[r * 16 + i], fac2[r * 16 + i + 1]);
    } else if (tid < 150) {              // fac3
        int k = tid - 75;
        int i = k / RANK, r = k % RANK;
        s_t3[k] = make_float2(fac3[r * 16 + i], fac3[r * 16 + i + 1]);
    } else if (tid < 225) {              // fac4
        int k = tid - 150;
        int i = k / RANK, r = k % RANK;
        s_t4[k] = make_float2(fac4[r * 16 + i], fac4[r * 16 + i + 1]);
    }
    if (tid >= 225 && tid < 240) {       // fac0 transposed float4
        int k = tid - 225;               // k = r*3+q
        int r = k / 3, q = k % 3;
        s_fac0[k] = make_float4(fac0[(4 * q + 0) * RANK + r],
                                fac0[(4 * q + 1) * RANK + r],
                                fac0[(4 * q + 2) * RANK + r],
                                fac0[(4 * q + 3) * RANK + r]);
    }
    if (tid >= 240 && tid < 248) {       // MLP layer 1 packed
        int h = tid - 240;
        s_mw[h] = make_float4(w1[h * 3 + 0], w1[h * 3 + 1], w1[h * 3 + 2], b1[h]);
    }
    if (tid == 248) s_w2[0] = make_float4(w2[0], w2[1], w2[2], w2[3]);
    if (tid == 249) s_w2[1] = make_float4(w2[4], w2[5], w2[6], w2[7]);
    if (tid == 250) s_b2 = b2[0];
    __syncthreads();

    int i = blockIdx.x * THREADS + tid;
    if (i >= npts) return;

    float x  = xyz[3 * i + 0];
    float y  = xyz[3 * i + 1];
    float z  = xyz[3 * i + 2];
    float r0 = rgb[3 * i + 0];
    float g0 = rgb[3 * i + 1];
    float b0 = rgb[3 * i + 2];

    // ---- rgb -> gray MLP (11 LDS.128) ----
    float acc = s_b2;
    float w2v[8];
    { float4 a = s_w2[0]; w2v[0]=a.x; w2v[1]=a.y; w2v[2]=a.z; w2v[3]=a.w; }
    { float4 a = s_w2[1]; w2v[4]=a.x; w2v[5]=a.y; w2v[6]=a.z; w2v[7]=a.w; }
#pragma unroll
    for (int h = 0; h < 8; h++) {
        float4 mw = s_mw[h];
        float hv = fmaf(mw.x, r0, fmaf(mw.y, g0, fmaf(mw.z, b0, mw.w)));
        hv = fmaxf(hv, 0.0f);
        acc = fmaf(w2v[h], hv, acc);
    }
    float gray = fast_tanh2(acc);

    // ---- CP factor products ----
    // pos = (v/BOUND + 1) * 0.5 * (D-1), BOUND=2 -> pos = v*0.25*(D-1) + 0.5*(D-1)
    float coef[RANK];
    interp_mul_pt(s_t1, 8,  fmaf(x, 1.75f, 3.5f), coef, true);
    interp_mul_pt(s_t2, 16, fmaf(y, 3.75f, 7.5f), coef, false);
    interp_mul_pt(s_t3, 16, fmaf(z, 3.75f, 7.5f), coef, false);
    interp_mul_pt(s_t4, 16, fmaf(gray, 7.5f, 7.5f), coef, false);

    // ---- 5 -> 12 linear via transposed float4 fac0 (15 LDS.128) ----
    float4 o[3];
#pragma unroll
    for (int q = 0; q < 3; q++) {
        float4 f = s_fac0[q];            // r = 0
        o[q].x = coef[0] * f.x;
        o[q].y = coef[0] * f.y;
        o[q].z = coef[0] * f.z;
        o[q].w = coef[0] * f.w;
    }
#pragma unroll
    for (int r = 1; r < RANK; r++) {
#pragma unroll
        for (int q = 0; q < 3; q++) {
            float4 f = s_fac0[r * 3 + q];
            o[q].x = fmaf(coef[r], f.x, o[q].x);
            o[q].y = fmaf(coef[r], f.y, o[q].y);
            o[q].z = fmaf(coef[r], f.z, o[q].z);
            o[q].w = fmaf(coef[r], f.w, o[q].w);
        }
    }

    int base = 3 * i;
    out4[base + 0] = o[0];
    out4[base + 1] = o[1];
    out4[base + 2] = o[2];
}

extern "C" void kernel_launch(void* const* d_in, const int* in_sizes, int n_in,
                              void* d_out, int out_size)
{
    const float* xyz  = (const float*)d_in[0];
    const float* rgb  = (const float*)d_in[1];
    const float* fac0 = (const float*)d_in[2];
    const float* fac1 = (const float*)d_in[3];
    const float* fac2 = (const float*)d_in[4];
    const float* fac3 = (const float*)d_in[5];
    const float* fac4 = (const float*)d_in[6];
    const float* w1   = (const float*)d_in[7];
    const float* b1   = (const float*)d_in[8];
    const float* w2   = (const float*)d_in[9];
    const float* b2   = (const float*)d_in[10];
    float4* out4 = (float4*)d_out;

    int npts = in_sizes[0] / 3;
    int blocks = (npts + THREADS - 1) / THREADS;
    bgrid_cp4d_kernel<<<blocks, THREADS>>>(xyz, rgb, fac0, fac1, fac2, fac3, fac4,
                                           w1, b1, w2, b2, out4, npts);
}

// round 4
// speedup vs baseline: 1.0841x; 1.0841x over previous
#include <cuda_runtime.h>
#include <cuda_bf16.h>

// BilateralGridCP4D fused eval, 1 point/thread.
// Round-4 change: uniform parameters (fac0, MLP weights) moved to __constant__
// memory -> LDC/LDCU uniform path, removing ~26 broadcast wavefronts/warp from
// the L1tex crossbar (which ncu shows as the binding pipe at 75%).
// Divergent interp gathers stay in shared memory (fp32 pair tables).

#define RANK 5
#define THREADS 256

__constant__ float c_fac0[60];   // (12,5) row-major
__constant__ float c_w1[24];     // (8,3)
__constant__ float c_b1[8];
__constant__ float c_w2[8];
__constant__ float c_b2[1];

__device__ __forceinline__ void interp_mul_pt(const float2* __restrict__ pt, int D,
                                              float pos, float coef[RANK], bool first)
{
    pos = fminf(fmaxf(pos, 0.0f), (float)(D - 1));
    int i0 = (int)pos;
    if (i0 > D - 2) i0 = D - 2;
    float w = pos - (float)i0;
    const float2* p = pt + i0 * RANK;
#pragma unroll
    for (int r = 0; r < RANK; r++) {
        float2 f = p[r];
        float val = fmaf(w, f.y - f.x, f.x);   // f0*(1-w) + f1*w
        if (first) coef[r] = val;
        else       coef[r] *= val;
    }
}

// tanh(2a) = 1 - 2/(exp(4a)+1), via MUFU. Rel err ~1e-6.
__device__ __forceinline__ float fast_tanh2(float a)
{
    float e = __expf(4.0f * a);
    return 1.0f - __fdividef(2.0f, e + 1.0f);
}

__global__ __launch_bounds__(THREADS)
void bgrid_cp4d_kernel(const float* __restrict__ xyz,
                       const float* __restrict__ rgb,
                       const float* __restrict__ fac1,  // (5,8)
                       const float* __restrict__ fac2,  // (5,16)
                       const float* __restrict__ fac3,  // (5,16)
                       const float* __restrict__ fac4,  // (5,16)
                       float4* __restrict__ out4,       // N*3 float4
                       int npts)
{
    // pair tables: pt[i*RANK + r] = (fac[r][i], fac[r][i+1])
    __shared__ float2 s_t1[7 * RANK];    // D=8
    __shared__ float2 s_t2[15 * RANK];   // D=16
    __shared__ float2 s_t3[15 * RANK];
    __shared__ float2 s_t4[15 * RANK];

    int tid = threadIdx.x;
    if (tid < 35) {
        int i = tid / RANK, r = tid % RANK;
        s_t1[tid] = make_float2(fac1[r * 8 + i], fac1[r * 8 + i + 1]);
    }
    if (tid < 75) {
        int i = tid / RANK, r = tid % RANK;
        s_t2[tid] = make_float2(fac2[r * 16 + i], fac2[r * 16 + i + 1]);
    } else if (tid < 150) {
        int k = tid - 75;
        int i = k / RANK, r = k % RANK;
        s_t3[k] = make_float2(fac3[r * 16 + i], fac3[r * 16 + i + 1]);
    } else if (tid < 225) {
        int k = tid - 150;
        int i = k / RANK, r = k % RANK;
        s_t4[k] = make_float2(fac4[r * 16 + i], fac4[r * 16 + i + 1]);
    }
    __syncthreads();

    int i = blockIdx.x * THREADS + tid;
    if (i >= npts) return;

    float x  = xyz[3 * i + 0];
    float y  = xyz[3 * i + 1];
    float z  = xyz[3 * i + 2];
    float r0 = rgb[3 * i + 0];
    float g0 = rgb[3 * i + 1];
    float b0 = rgb[3 * i + 2];

    // ---- rgb -> gray MLP (weights via uniform constant path, no L1tex) ----
    float acc = c_b2[0];
#pragma unroll
    for (int h = 0; h < 8; h++) {
        float hv = fmaf(c_w1[h * 3 + 0], r0,
                   fmaf(c_w1[h * 3 + 1], g0,
                   fmaf(c_w1[h * 3 + 2], b0, c_b1[h])));
        hv = fmaxf(hv, 0.0f);
        acc = fmaf(c_w2[h], hv, acc);
    }
    float gray = fast_tanh2(acc);

    // ---- CP factor products ----
    // pos = (v/BOUND + 1)*0.5*(D-1), BOUND=2 -> pos = v*0.25*(D-1) + 0.5*(D-1)
    float coef[RANK];
    interp_mul_pt(s_t1, 8,  fmaf(x, 1.75f, 3.5f), coef, true);
    interp_mul_pt(s_t2, 16, fmaf(y, 3.75f, 7.5f), coef, false);
    interp_mul_pt(s_t3, 16, fmaf(z, 3.75f, 7.5f), coef, false);
    interp_mul_pt(s_t4, 16, fmaf(gray, 7.5f, 7.5f), coef, false);

    // ---- 5 -> 12 linear via constant fac0 (compile-time indices -> LDCU) ----
    float4 o[3];
#pragma unroll
    for (int q = 0; q < 3; q++) {
        o[q].x = coef[0] * c_fac0[(4 * q + 0) * RANK];
        o[q].y = coef[0] * c_fac0[(4 * q + 1) * RANK];
        o[q].z = coef[0] * c_fac0[(4 * q + 2) * RANK];
        o[q].w = coef[0] * c_fac0[(4 * q + 3) * RANK];
    }
#pragma unroll
    for (int r = 1; r < RANK; r++) {
#pragma unroll
        for (int q = 0; q < 3; q++) {
            o[q].x = fmaf(coef[r], c_fac0[(4 * q + 0) * RANK + r], o[q].x);
            o[q].y = fmaf(coef[r], c_fac0[(4 * q + 1) * RANK + r], o[q].y);
            o[q].z = fmaf(coef[r], c_fac0[(4 * q + 2) * RANK + r], o[q].z);
            o[q].w = fmaf(coef[r], c_fac0[(4 * q + 3) * RANK + r], o[q].w);
        }
    }

    int base = 3 * i;
    out4[base + 0] = o[0];
    out4[base + 1] = o[1];
    out4[base + 2] = o[2];
}

extern "C" void kernel_launch(void* const* d_in, const int* in_sizes, int n_in,
                              void* d_out, int out_size)
{
    const float* xyz  = (const float*)d_in[0];
    const float* rgb  = (const float*)d_in[1];
    const float* fac1 = (const float*)d_in[3];
    const float* fac2 = (const float*)d_in[4];
    const float* fac3 = (const float*)d_in[5];
    const float* fac4 = (const float*)d_in[6];
    float4* out4 = (float4*)d_out;

    // Uniform params -> constant memory (D2D async copies, graph-capturable)
    cudaMemcpyToSymbolAsync(c_fac0, d_in[2], 60 * sizeof(float), 0,
                            cudaMemcpyDeviceToDevice, 0);
    cudaMemcpyToSymbolAsync(c_w1,   d_in[7], 24 * sizeof(float), 0,
                            cudaMemcpyDeviceToDevice, 0);
    cudaMemcpyToSymbolAsync(c_b1,   d_in[8],  8 * sizeof(float), 0,
                            cudaMemcpyDeviceToDevice, 0);
    cudaMemcpyToSymbolAsync(c_w2,   d_in[9],  8 * sizeof(float), 0,
                            cudaMemcpyDeviceToDevice, 0);
    cudaMemcpyToSymbolAsync(c_b2,   d_in[10], 1 * sizeof(float), 0,
                            cudaMemcpyDeviceToDevice, 0);

    int npts = in_sizes[0] / 3;
    int blocks = (npts + THREADS - 1) / THREADS;
    bgrid_cp4d_kernel<<<blocks, THREADS>>>(xyz, rgb, fac1, fac2, fac3, fac4,
                                           out4, npts);
}

// round 5
// speedup vs baseline: 1.1920x; 1.0995x over previous
#include <cuda_runtime.h>
#include <cuda_bf16.h>

// BilateralGridCP4D fused eval, 1 point/thread.
// Round-5: (a) single combined __constant__ block filled via one setup-kernel
// + one memcpy node (was 5 memcpy nodes ~14.5us of graph overhead);
// (b) final 5->12 linear in packed fma.rn.f32x2 (60 FFMA -> 30 FFMA2);
// (c) interp tables store (base, delta) to drop the per-lerp subtract.

#define RANK 5
#define THREADS 256

// layout: [0..59] fac0^T (idx = r*12 + j), [60..91] (w1[h][0..2],b1[h]) per h,
//         [92..99] w2, [100] b2
__constant__ float c_params[104];
__device__   float g_staging[104];

using u64 = unsigned long long;

__device__ __forceinline__ u64 pack2(float a, float b) {
    u64 d; asm("mov.b64 %0,{%1,%2};" : "=l"(d) : "f"(a), "f"(b)); return d;
}
__device__ __forceinline__ void unpack2(u64 v, float& a, float& b) {
    asm("mov.b64 {%0,%1},%2;" : "=f"(a), "=f"(b) : "l"(v));
}
__device__ __forceinline__ u64 fma2(u64 a, u64 b, u64 c) {
    u64 d; asm("fma.rn.f32x2 %0,%1,%2,%3;" : "=l"(d) : "l"(a), "l"(b), "l"(c)); return d;
}
__device__ __forceinline__ u64 mul2(u64 a, u64 b) {
    u64 d; asm("mul.rn.f32x2 %0,%1,%2;" : "=l"(d) : "l"(a), "l"(b)); return d;
}

__global__ void setup_kernel(const float* __restrict__ fac0,
                             const float* __restrict__ w1,
                             const float* __restrict__ b1,
                             const float* __restrict__ w2,
                             const float* __restrict__ b2)
{
    int t = threadIdx.x;
    if (t < 60) {                        // fac0 transpose: [r][j] <- fac0[j][r]
        int r = t / 12, j = t % 12;
        g_staging[t] = fac0[j * RANK + r];
    } else if (t < 92) {                 // (w1 row, b1) packed per hidden unit
        int k = t - 60, h = k / 4, c = k % 4;
        g_staging[t] = (c < 3) ? w1[h * 3 + c] : b1[h];
    } else if (t < 100) {
        g_staging[t] = w2[t - 92];
    } else if (t == 100) {
        g_staging[100] = b2[0];
    }
}

// pt[i*RANK + r] = (f0, f1-f0); val = f0 + w*delta
__device__ __forceinline__ void interp_mul_pt(const float2* __restrict__ pt, int D,
                                              float pos, float coef[RANK], bool first)
{
    pos = fminf(fmaxf(pos, 0.0f), (float)(D - 1));
    int i0 = (int)pos;
    if (i0 > D - 2) i0 = D - 2;
    float w = pos - (float)i0;
    const float2* p = pt + i0 * RANK;
#pragma unroll
    for (int r = 0; r < RANK; r++) {
        float2 f = p[r];
        float val = fmaf(w, f.y, f.x);
        if (first) coef[r] = val;
        else       coef[r] *= val;
    }
}

// tanh(2a) = 1 - 2/(exp(4a)+1), via MUFU. Rel err ~1e-6.
__device__ __forceinline__ float fast_tanh2(float a)
{
    float e = __expf(4.0f * a);
    return 1.0f - __fdividef(2.0f, e + 1.0f);
}

__global__ __launch_bounds__(THREADS)
void bgrid_cp4d_kernel(const float* __restrict__ xyz,
                       const float* __restrict__ rgb,
                       const float* __restrict__ fac1,  // (5,8)
                       const float* __restrict__ fac2,  // (5,16)
                       const float* __restrict__ fac3,  // (5,16)
                       const float* __restrict__ fac4,  // (5,16)
                       float4* __restrict__ out4,       // N*3 float4
                       int npts)
{
    __shared__ float2 s_t1[7 * RANK];    // D=8
    __shared__ float2 s_t2[15 * RANK];   // D=16
    __shared__ float2 s_t3[15 * RANK];
    __shared__ float2 s_t4[15 * RANK];

    int tid = threadIdx.x;
    if (tid < 35) {
        int i = tid / RANK, r = tid % RANK;
        float a = fac1[r * 8 + i], b = fac1[r * 8 + i + 1];
        s_t1[tid] = make_float2(a, b - a);
    }
    if (tid < 75) {
        int i = tid / RANK, r = tid % RANK;
        float a = fac2[r * 16 + i], b = fac2[r * 16 + i + 1];
        s_t2[tid] = make_float2(a, b - a);
    } else if (tid < 150) {
        int k = tid - 75, i = k / RANK, r = k % RANK;
        float a = fac3[r * 16 + i], b = fac3[r * 16 + i + 1];
        s_t3[k] = make_float2(a, b - a);
    } else if (tid < 225) {
        int k = tid - 150, i = k / RANK, r = k % RANK;
        float a = fac4[r * 16 + i], b = fac4[r * 16 + i + 1];
        s_t4[k] = make_float2(a, b - a);
    }
    __syncthreads();

    int i = blockIdx.x * THREADS + tid;
    if (i >= npts) return;

    float x  = xyz[3 * i + 0];
    float y  = xyz[3 * i + 1];
    float z  = xyz[3 * i + 2];
    float r0 = rgb[3 * i + 0];
    float g0 = rgb[3 * i + 1];
    float b0 = rgb[3 * i + 2];

    // ---- rgb -> gray MLP (constant/uniform path, no L1tex) ----
    float acc = c_params[100];
#pragma unroll
    for (int h = 0; h < 8; h++) {
        const float4 mw = *reinterpret_cast<const float4*>(&c_params[60 + 4 * h]);
        float hv = fmaf(mw.x, r0, fmaf(mw.y, g0, fmaf(mw.z, b0, mw.w)));
        hv = fmaxf(hv, 0.0f);
        acc = fmaf(c_params[92 + h], hv, acc);
    }
    float gray = fast_tanh2(acc);

    // ---- CP factor products (pos = v*0.25*(D-1) + 0.5*(D-1), BOUND=2) ----
    float coef[RANK];
    interp_mul_pt(s_t1, 8,  fmaf(x, 1.75f, 3.5f), coef, true);
    interp_mul_pt(s_t2, 16, fmaf(y, 3.75f, 7.5f), coef, false);
    interp_mul_pt(s_t3, 16, fmaf(z, 3.75f, 7.5f), coef, false);
    interp_mul_pt(s_t4, 16, fmaf(gray, 7.5f, 7.5f), coef, false);

    // ---- 5 -> 12 linear via packed f32x2 (fac0^T pairs from constant) ----
    u64 op[6];
    {
        u64 cc = pack2(coef[0], coef[0]);
#pragma unroll
        for (int q = 0; q < 6; q++) {
            u64 f = *reinterpret_cast<const u64*>(&c_params[0 * 12 + 2 * q]);
            op[q] = mul2(cc, f);
        }
    }
#pragma unroll
    for (int r = 1; r < RANK; r++) {
        u64 cc = pack2(coef[r], coef[r]);
#pragma unroll
        for (int q = 0; q < 6; q++) {
            u64 f = *reinterpret_cast<const u64*>(&c_params[r * 12 + 2 * q]);
            op[q] = fma2(cc, f, op[q]);
        }
    }

    float o[12];
#pragma unroll
    for (int q = 0; q < 6; q++)
        unpack2(op[q], o[2 * q], o[2 * q + 1]);

    int base = 3 * i;
    out4[base + 0] = make_float4(o[0], o[1], o[2],  o[3]);
    out4[base + 1] = make_float4(o[4], o[5], o[6],  o[7]);
    out4[base + 2] = make_float4(o[8], o[9], o[10], o[11]);
}

extern "C" void kernel_launch(void* const* d_in, const int* in_sizes, int n_in,
                              void* d_out, int out_size)
{
    const float* xyz  = (const float*)d_in[0];
    const float* rgb  = (const float*)d_in[1];
    const float* fac1 = (const float*)d_in[3];
    const float* fac2 = (const float*)d_in[4];
    const float* fac3 = (const float*)d_in[5];
    const float* fac4 = (const float*)d_in[6];
    float4* out4 = (float4*)d_out;

    // Gather all uniform params into staging (one kernel node) ...
    setup_kernel<<<1, 128>>>((const float*)d_in[2], (const float*)d_in[7],
                             (const float*)d_in[8], (const float*)d_in[9],
                             (const float*)d_in[10]);
    // ... then one memcpy node into constant memory.
    void* staging_ptr = nullptr;
    cudaGetSymbolAddress(&staging_ptr, g_staging);
    cudaMemcpyToSymbolAsync(c_params, staging_ptr, 101 * sizeof(float), 0,
                            cudaMemcpyDeviceToDevice, 0);

    int npts = in_sizes[0] / 3;
    int blocks = (npts + THREADS - 1) / THREADS;
    bgrid_cp4d_kernel<<<blocks, THREADS>>>(xyz, rgb, fac1, fac2, fac3, fac4,
                                           out4, npts);
}